// round 1
// baseline (speedup 1.0000x reference)
#include <cuda_runtime.h>
#include <math.h>

#define BB 8
#define TT 4096
#define DD 512
#define UU 768
#define LL 4
#define VV 256
#define DFFC 2048
#define MM (BB*TT)          // 32768 rows
#define NSCAN 128           // persistent scan CTAs (must all be co-resident)

// ---------------- scratch (device globals; no cudaMalloc allowed) ----------
__device__ float g_x[MM*DD];            // residual stream (B,T,D)
__device__ float g_nrm[MM*DD];          // layernorm output
__device__ float g_xpre[4][TT*BB*UU];   // 4 gate pre-activations, (T,B,U)
__device__ float g_cfc[MM*DD];          // scan output (B,T,D)
__device__ float g_mid[MM*DFFC];        // MLP hidden
__device__ float g_h[2][BB*UU];         // recurrent state double buffer
__device__ float g_loss[2];             // {sum nll, count}
__device__ unsigned int g_bar;          // grid barrier counter (monotonic per launch)

// ---------------- embedding ------------------------------------------------
__global__ void embed_k(const int* __restrict__ idx, const float* __restrict__ wte) {
    int e = blockIdx.x*256 + threadIdx.x;        // one float4 per thread
    int row = e >> 7;                            // 128 float4 per row (D=512)
    int c = e & 127;
    int tok = idx[row];
    reinterpret_cast<float4*>(g_x)[e] =
        reinterpret_cast<const float4*>(wte)[tok*128 + c];
}

// ---------------- layernorm (one block of 128 threads per row) -------------
__global__ void ln_k(const float* __restrict__ in, const float* __restrict__ s,
                     const float* __restrict__ b, float* __restrict__ out) {
    __shared__ float red[8];
    int row = blockIdx.x;
    const float* x = in + (size_t)row*DD;
    float v[4]; float sum = 0.f, sq = 0.f;
#pragma unroll
    for (int j=0;j<4;j++) { v[j] = x[threadIdx.x + j*128]; sum += v[j]; sq += v[j]*v[j]; }
#pragma unroll
    for (int off=16; off; off>>=1) {
        sum += __shfl_xor_sync(0xffffffffu, sum, off);
        sq  += __shfl_xor_sync(0xffffffffu, sq,  off);
    }
    int w = threadIdx.x >> 5, lane = threadIdx.x & 31;
    if (lane == 0) { red[w] = sum; red[4+w] = sq; }
    __syncthreads();
    if (threadIdx.x == 0) {
        red[0] = red[0]+red[1]+red[2]+red[3];
        red[4] = red[4]+red[5]+red[6]+red[7];
    }
    __syncthreads();
    float mean = red[0]*(1.f/512.f);
    float var  = red[4]*(1.f/512.f) - mean*mean;
    float r = rsqrtf(var + 1e-5f);
#pragma unroll
    for (int j=0;j<4;j++) {
        int d = threadIdx.x + j*128;
        out[(size_t)row*DD + d] = (v[j]-mean)*r*s[d] + b[d];
    }
}

// ---------------- SGEMM 128x128x16, 8x8/thread -----------------------------
// EPI: 0 = C[m*N+n] = acc(+bias)        (logits)
//      1 = xpre layout (T,B,U): C[t*B*U + b*U + n] = acc + bias   (projections)
//      2 = C[m*N+n] = gelu(acc + bias)  (MLP1)
//      3 = C[m*N+n] = R[m*N+n] + acc + bias  (MLP2 + residual)
// BTR: B stored (N,K) row-major (logits: wte)
template<int EPI, bool BTR>
__global__ void __launch_bounds__(256) gemm_k(
    const float* __restrict__ A, const float* __restrict__ B,
    const float* __restrict__ bias, const float* __restrict__ R,
    float* __restrict__ C, int M, int N, int K)
{
    __shared__ float As[16][128];
    __shared__ float Bs[16][128];
    const int tid = threadIdx.x;
    const int tx = tid & 15, ty = tid >> 4;
    const int m0 = blockIdx.y << 7, n0 = blockIdx.x << 7;
    float acc[8][8];
#pragma unroll
    for (int i=0;i<8;i++)
#pragma unroll
        for (int j=0;j<8;j++) acc[i][j] = 0.f;

    const int aRow = tid >> 2, aCol = tid & 3;
    const int bRow = tid >> 5, bCol = tid & 31;

    for (int k0 = 0; k0 < K; k0 += 16) {
#pragma unroll
        for (int h=0; h<2; h++) {
            float4 av = *reinterpret_cast<const float4*>(
                &A[(size_t)(m0 + aRow + h*64)*K + k0 + aCol*4]);
            As[aCol*4+0][aRow+h*64] = av.x;
            As[aCol*4+1][aRow+h*64] = av.y;
            As[aCol*4+2][aRow+h*64] = av.z;
            As[aCol*4+3][aRow+h*64] = av.w;
        }
        if (!BTR) {
#pragma unroll
            for (int h=0; h<2; h++) {
                float4 bv = *reinterpret_cast<const float4*>(
                    &B[(size_t)(k0 + bRow + h*8)*N + n0 + bCol*4]);
                *reinterpret_cast<float4*>(&Bs[bRow+h*8][bCol*4]) = bv;
            }
        } else {
#pragma unroll
            for (int h=0; h<2; h++) {
                int n = (tid>>2) + h*64, kc = (tid&3)*4;
                float4 bv = *reinterpret_cast<const float4*>(
                    &B[(size_t)(n0+n)*K + k0 + kc]);
                Bs[kc+0][n]=bv.x; Bs[kc+1][n]=bv.y; Bs[kc+2][n]=bv.z; Bs[kc+3][n]=bv.w;
            }
        }
        __syncthreads();
#pragma unroll
        for (int k=0;k<16;k++) {
            float ra[8], rb[8];
            *reinterpret_cast<float4*>(ra)   = *reinterpret_cast<const float4*>(&As[k][ty*8]);
            *reinterpret_cast<float4*>(ra+4) = *reinterpret_cast<const float4*>(&As[k][ty*8+4]);
            *reinterpret_cast<float4*>(rb)   = *reinterpret_cast<const float4*>(&Bs[k][tx*8]);
            *reinterpret_cast<float4*>(rb+4) = *reinterpret_cast<const float4*>(&Bs[k][tx*8+4]);
#pragma unroll
            for (int i=0;i<8;i++)
#pragma unroll
                for (int j=0;j<8;j++) acc[i][j] = fmaf(ra[i], rb[j], acc[i][j]);
        }
        __syncthreads();
    }

    float bn[8];
#pragma unroll
    for (int j=0;j<8;j++) bn[j] = bias ? bias[n0 + tx*8 + j] : 0.f;

#pragma unroll
    for (int i=0;i<8;i++) {
        int m = m0 + ty*8 + i;
#pragma unroll
        for (int j4=0;j4<2;j4++) {
            float4 v;
            float* vv = &v.x;
#pragma unroll
            for (int j=0;j<4;j++) {
                float t = acc[i][j4*4+j] + bn[j4*4+j];
                if (EPI == 2) t = 0.5f*t*(1.f + erff(t*0.70710678118654752f));
                vv[j] = t;
            }
            int n = n0 + tx*8 + j4*4;
            if (EPI == 1) {
                int b_ = m >> 12, t_ = m & 4095;     // m = b*T + t, T=4096
                *reinterpret_cast<float4*>(&C[(size_t)t_*(BB*UU) + b_*UU + n]) = v;
            } else if (EPI == 3) {
                float4 r = *reinterpret_cast<const float4*>(&R[(size_t)m*N + n]);
                v.x += r.x; v.y += r.y; v.z += r.z; v.w += r.w;
                *reinterpret_cast<float4*>(&C[(size_t)m*N + n]) = v;
            } else {
                *reinterpret_cast<float4*>(&C[(size_t)m*N + n]) = v;
            }
        }
    }
}

// ---------------- persistent CfC scan (128 CTAs x 384 threads) -------------
// CTA owns 6 u-columns; warp pair (2 warps) per u, k split 384/384.
// Recurrent weights live in registers for the whole 4096-step loop.
__global__ void __launch_bounds__(384, 1) scan_k(
    const float* __restrict__ Wh1, const float* __restrict__ Wh2,
    const float* __restrict__ Wha, const float* __restrict__ Whb,
    const float* __restrict__ x1,  const float* __restrict__ x2,
    const float* __restrict__ xa,  const float* __restrict__ xb)
{
    __shared__ float hs[BB*UU];        // 24KB: current h
    __shared__ float part[12][8][4];   // per-warp partial sums
    const int tid  = threadIdx.x;
    const int w    = tid >> 5, lane = tid & 31;
    const int ul   = w >> 1;                     // local u 0..5
    const int u    = blockIdx.x*6 + ul;
    const int kbase = (w & 1)*384 + lane;        // this lane's k stride-32 set

    float w1[12], w2[12], wa[12], wb[12];
#pragma unroll
    for (int j=0;j<12;j++) {
        int k = kbase + 32*j;
        w1[j] = Wh1[k*UU + u];
        w2[j] = Wh2[k*UU + u];
        wa[j] = Wha[k*UU + u];
        wb[j] = Whb[k*UU + u];
    }

    const int fu  = tid / 8;                // final-stage mapping (tid<48)
    const int fB  = tid & 7;
    const int fug = blockIdx.x*6 + fu;

    for (int t = 0; t < TT; t++) {
        // prefetch this step's gate pre-activations (overlaps with dot products)
        float p1=0.f, p2=0.f, pa=0.f, pb=0.f;
        if (tid < 48) {
            int xi = t*(BB*UU) + fB*UU + fug;
            p1 = x1[xi]; p2 = x2[xi]; pa = xa[xi]; pb = xb[xi];
        }
        // load h (L2-coherent) into smem
        if (t == 0) {
            for (int p = tid; p < BB*UU; p += 384) hs[p] = 0.f;
        } else {
            const float4* src = reinterpret_cast<const float4*>(g_h[t & 1]);
            float4* dst = reinterpret_cast<float4*>(hs);
            for (int p = tid; p < BB*UU/4; p += 384) dst[p] = __ldcg(&src[p]);
        }
        __syncthreads();

#pragma unroll
        for (int b=0;b<8;b++) {
            float a1=0.f, a2=0.f, aa=0.f, ab=0.f;
            const float* hb = &hs[b*UU + kbase];
#pragma unroll
            for (int j=0;j<12;j++) {
                float hv = hb[32*j];
                a1 = fmaf(w1[j], hv, a1); a2 = fmaf(w2[j], hv, a2);
                aa = fmaf(wa[j], hv, aa); ab = fmaf(wb[j], hv, ab);
            }
#pragma unroll
            for (int off=16; off; off>>=1) {
                a1 += __shfl_xor_sync(0xffffffffu, a1, off);
                a2 += __shfl_xor_sync(0xffffffffu, a2, off);
                aa += __shfl_xor_sync(0xffffffffu, aa, off);
                ab += __shfl_xor_sync(0xffffffffu, ab, off);
            }
            if (lane == 0) {
                part[w][b][0]=a1; part[w][b][1]=a2; part[w][b][2]=aa; part[w][b][3]=ab;
            }
        }
        __syncthreads();

        if (tid < 48) {
            float s1 = part[2*fu][fB][0] + part[2*fu+1][fB][0] + p1;
            float s2 = part[2*fu][fB][1] + part[2*fu+1][fB][1] + p2;
            float sa = part[2*fu][fB][2] + part[2*fu+1][fB][2] + pa;
            float sb = part[2*fu][fB][3] + part[2*fu+1][fB][3] + pb;
            float f1 = tanhf(s1), f2 = tanhf(s2);
            float ti = 1.f/(1.f + expf(-(sa+sb)));
            float hn = f1 + ti*(f2 - f1);
            __stcg(&g_h[1-(t&1)][fB*UU + fug], hn);
            if (fug < DD) g_cfc[((size_t)fB*TT + t)*DD + fug] = hn;
        }
        __syncthreads();
        if (tid == 0) {                 // chip-wide barrier: monotonic counter
            __threadfence();
            atomicAdd(&g_bar, 1u);
            unsigned target = (unsigned)(t+1)*NSCAN;
            while (*reinterpret_cast<volatile unsigned*>(&g_bar) < target) {}
            __threadfence();
        }
        __syncthreads();
    }
}

// ---------------- LIF gate + residual add ----------------------------------
__global__ void lif_k(const float* __restrict__ thr_p,
                      const float* __restrict__ leak_p,
                      const float* __restrict__ steep_p) {
    int e = blockIdx.x*256 + threadIdx.x;
    int d = e & 511;
    float thr  = fabsf(thr_p[d]) * 0.1f;
    float leak = 1.f/(1.f + expf(-leak_p[d]));
    float sv = steep_p[d];
    float steep = (sv > 20.f) ? sv : log1pf(expf(sv));
    float c = g_cfc[e];
    float fire = 1.f/(1.f + expf(-steep*(fabsf(c) - thr)));
    float gate = fire + leak*(1.f - fire);
    g_x[e] += c*gate;
}

// ---------------- loss: one warp per row of 256 logits ----------------------
__global__ void loss_k(const int* __restrict__ tgt, const float* __restrict__ logits) {
    int row  = blockIdx.x*8 + (threadIdx.x >> 5);
    int lane = threadIdx.x & 31;
    const float* lr = logits + (size_t)row*VV;
    float v[8]; float mx = -3.4e38f;
#pragma unroll
    for (int j=0;j<8;j++) { v[j] = lr[lane + 32*j]; mx = fmaxf(mx, v[j]); }
#pragma unroll
    for (int off=16; off; off>>=1) mx = fmaxf(mx, __shfl_xor_sync(0xffffffffu, mx, off));
    float se = 0.f;
#pragma unroll
    for (int j=0;j<8;j++) se += expf(v[j]-mx);
#pragma unroll
    for (int off=16; off; off>>=1) se += __shfl_xor_sync(0xffffffffu, se, off);
    if (lane == 0) {
        int tv = tgt[row];
        if (tv >= 0) {
            float nll = mx + logf(se) - lr[tv];
            atomicAdd(&g_loss[0], nll);
            atomicAdd(&g_loss[1], 1.f);
        }
    }
}

__global__ void fin_k(float* __restrict__ out, int out_size) {
    if (out_size > MM*VV) out[MM*VV] = g_loss[0]/g_loss[1];
}

__global__ void zero_k() { g_bar = 0u; g_loss[0] = 0.f; g_loss[1] = 0.f; }

// ---------------- driver ----------------------------------------------------
extern "C" void kernel_launch(void* const* d_in, const int* in_sizes, int n_in,
                              void* d_out, int out_size) {
    (void)in_sizes; (void)n_in;
    const int*   idx      = (const int*)  d_in[0];
    const int*   targets  = (const int*)  d_in[1];
    const float* wte      = (const float*)d_in[2];
    const float* ln1_s    = (const float*)d_in[3];
    const float* ln1_b    = (const float*)d_in[4];
    const float* Wff1     = (const float*)d_in[5];
    const float* bff1     = (const float*)d_in[6];
    const float* Wff2     = (const float*)d_in[7];
    const float* bff2     = (const float*)d_in[8];
    const float* Wta      = (const float*)d_in[9];
    const float* bta      = (const float*)d_in[10];
    const float* Wtb      = (const float*)d_in[11];
    const float* btb      = (const float*)d_in[12];
    const float* lif_thr  = (const float*)d_in[13];
    const float* lif_leak = (const float*)d_in[14];
    const float* lif_stp  = (const float*)d_in[15];
    const float* ln2_s    = (const float*)d_in[16];
    const float* ln2_b    = (const float*)d_in[17];
    const float* mW1      = (const float*)d_in[18];
    const float* mb1      = (const float*)d_in[19];
    const float* mW2      = (const float*)d_in[20];
    const float* mb2      = (const float*)d_in[21];
    const float* lnf_s    = (const float*)d_in[22];
    const float* lnf_b    = (const float*)d_in[23];
    float* out = (float*)d_out;

    float *xp, *nm, *mid, *xpre;
    cudaGetSymbolAddress((void**)&xp,   g_x);
    cudaGetSymbolAddress((void**)&nm,   g_nrm);
    cudaGetSymbolAddress((void**)&mid,  g_mid);
    cudaGetSymbolAddress((void**)&xpre, g_xpre);

    embed_k<<<MM*DD/4/256, 256>>>(idx, wte);

    const size_t WSTRIDE = (size_t)(DD+UU)*UU;   // per-layer stride of Wff*/Wt*
    const size_t XG = (size_t)TT*BB*UU;          // per-gate xpre stride

    for (int l = 0; l < LL; l++) {
        ln_k<<<MM,128>>>(xp, ln1_s + l*DD, ln1_b + l*DD, nm);

        const float* Wg[4] = {Wff1, Wff2, Wta, Wtb};
        const float* bg[4] = {bff1, bff2, bta, btb};
        for (int g = 0; g < 4; g++) {
            gemm_k<1,false><<<dim3(UU/128, MM/128), 256>>>(
                nm, Wg[g] + (size_t)l*WSTRIDE, bg[g] + l*UU, nullptr,
                xpre + (size_t)g*XG, MM, UU, DD);
        }

        zero_k<<<1,1>>>();
        scan_k<<<NSCAN, 384>>>(
            Wff1 + (size_t)l*WSTRIDE + (size_t)DD*UU,
            Wff2 + (size_t)l*WSTRIDE + (size_t)DD*UU,
            Wta  + (size_t)l*WSTRIDE + (size_t)DD*UU,
            Wtb  + (size_t)l*WSTRIDE + (size_t)DD*UU,
            xpre, xpre + XG, xpre + 2*XG, xpre + 3*XG);

        lif_k<<<MM*DD/256, 256>>>(lif_thr + l*DD, lif_leak + l*DD, lif_stp + l*DD);

        ln_k<<<MM,128>>>(xp, ln2_s + l*DD, ln2_b + l*DD, nm);
        gemm_k<2,false><<<dim3(DFFC/128, MM/128), 256>>>(
            nm, mW1 + (size_t)l*DD*DFFC, mb1 + l*DFFC, nullptr, mid, MM, DFFC, DD);
        gemm_k<3,false><<<dim3(DD/128, MM/128), 256>>>(
            mid, mW2 + (size_t)l*DFFC*DD, mb2 + l*DD, xp, xp, MM, DD, DFFC);
    }

    ln_k<<<MM,128>>>(xp, lnf_s, lnf_b, nm);
    gemm_k<0,true><<<dim3(VV/128, MM/128), 256>>>(
        nm, wte, nullptr, nullptr, out, MM, VV, DD);
    loss_k<<<MM/8, 256>>>(targets, out);
    fin_k<<<1,1>>>(out, out_size);
}